// round 1
// baseline (speedup 1.0000x reference)
#include <cuda_runtime.h>

#define BB 1024
#define LL 4096
#define DD 64
#define KK 64
#define NTHREADS 256

// Normalized mask scratch (allocation-free: __device__ global)
__device__ unsigned char g_mask[BB * LL];
__device__ int g_mask_mode; // 0 = int32 {0,1}, 1 = byte bool, 2 = float32 {0,1}

// ---------------------------------------------------------------------------
// Detect seq_mask storage dtype from raw word patterns (deterministic).
//  - int32 bool:  every 32-bit word is 0 or 1
//  - byte bool:   words combine four 0/1 bytes -> values >1 appear (never 0x3F800000)
//  - float bool:  words are 0x00000000 or 0x3F800000
// ---------------------------------------------------------------------------
__global__ void detect_mask_kernel(const unsigned int* __restrict__ m) {
    if (threadIdx.x == 0 && blockIdx.x == 0) {
        int mode = 0;
        for (int i = 0; i < 1024; i++) {
            unsigned int w = m[i];
            if (w == 0x3F800000u) { mode = 2; break; }
            if (w > 1u)           { mode = 1; break; }
        }
        g_mask_mode = mode;
    }
}

__global__ void normalize_mask_kernel(const void* __restrict__ m) {
    int i = blockIdx.x * blockDim.x + threadIdx.x;
    if (i >= BB * LL) return;
    int mode = g_mask_mode;
    unsigned char v;
    if (mode == 1) {
        v = ((const unsigned char*)m)[i] ? 1 : 0;
    } else if (mode == 2) {
        v = (((const float*)m)[i] != 0.0f) ? 1 : 0;
    } else {
        v = ((const int*)m)[i] ? 1 : 0;
    }
    g_mask[i] = v;
}

// ---------------------------------------------------------------------------
// Main kernel: one CTA per batch row.
//   1) q = (target_emb[b] @ W^T) * 0.125   (pre-scale by 1/sqrt(D), exact)
//   2) scores[l] = dot(seq_emb[b,l,:], q), masked -> -1e9
//   3) composite-key bitonic sort (descending) for exact lax.top_k semantics
//   4) gather top-64 embedding rows (bit-exact copy) + mask output
// ---------------------------------------------------------------------------
__global__ __launch_bounds__(NTHREADS) void gsu_main_kernel(
    const float* __restrict__ tgt,   // [B, D]
    const float* __restrict__ seq,   // [B, L, D]
    const float* __restrict__ W,     // [D, D]
    float* __restrict__ out_emb,     // [B, K, D]
    float* __restrict__ out_mask,    // [B, K] as float (optional)
    int write_mask)
{
    __shared__ float ts[DD];
    __shared__ float qs[DD];
    __shared__ unsigned long long keys[LL];

    const int b   = blockIdx.x;
    const int tid = threadIdx.x;

    // --- Step 1: q projection ---
    if (tid < DD) ts[tid] = tgt[b * DD + tid];
    __syncthreads();
    if (tid < DD) {
        const float* wr = W + tid * DD;
        float acc = 0.0f;
#pragma unroll
        for (int j = 0; j < DD; j++) acc += wr[j] * ts[j];
        qs[tid] = acc * 0.125f; // 1/sqrt(64): exact power-of-two scale
    }
    __syncthreads();

    // --- Step 2: scores + key encode ---
    const float4* q4   = (const float4*)qs;
    const float4* seqb = (const float4*)(seq + (size_t)b * LL * DD);
    const unsigned char* mb = g_mask + (size_t)b * LL;

#pragma unroll 1
    for (int r = 0; r < LL / NTHREADS; r++) {
        const int l = tid + r * NTHREADS;
        const float4* row = seqb + (size_t)l * (DD / 4);
        float a0 = 0.f, a1 = 0.f, a2 = 0.f, a3 = 0.f;
#pragma unroll
        for (int j = 0; j < DD / 4; j++) {
            float4 v = row[j];
            float4 qq = q4[j];
            a0 = fmaf(v.x, qq.x, a0);
            a1 = fmaf(v.y, qq.y, a1);
            a2 = fmaf(v.z, qq.z, a2);
            a3 = fmaf(v.w, qq.w, a3);
        }
        float s = (a0 + a1) + (a2 + a3);
        if (!mb[l]) s = -1e9f;
        // order-preserving float -> uint (monotonic increasing)
        unsigned int fu = __float_as_uint(s);
        fu = (fu & 0x80000000u) ? ~fu : (fu | 0x80000000u);
        // low word: smaller index -> larger value (jax tie-break: lower idx first)
        keys[l] = ((unsigned long long)fu << 32) |
                  (unsigned long long)(0xFFFFFFFFu ^ (unsigned int)l);
    }
    __syncthreads();

    // --- Step 3: bitonic sort DESCENDING on 4096 u64 keys ---
    for (int k = 2; k <= LL; k <<= 1) {
        for (int j = k >> 1; j > 0; j >>= 1) {
            for (int i = tid; i < LL; i += NTHREADS) {
                int ixj = i ^ j;
                if (ixj > i) {
                    unsigned long long a = keys[i];
                    unsigned long long c = keys[ixj];
                    bool desc = ((i & k) == 0);
                    if (desc ? (a < c) : (a > c)) {
                        keys[i]   = c;
                        keys[ixj] = a;
                    }
                }
            }
            __syncthreads();
        }
    }

    // --- Step 4: gather top-K rows (exact copy) ---
    float4* out4 = (float4*)(out_emb + (size_t)b * KK * DD);
    for (int i = tid; i < KK * DD / 4; i += NTHREADS) {
        int kk  = i >> 4;   // D/4 = 16 float4 per row
        int off = i & 15;
        unsigned int lowk = (unsigned int)keys[kk];
        int idx = (int)(0xFFFFFFFFu ^ lowk); // recover l
        out4[i] = seqb[(size_t)idx * (DD / 4) + off];
    }

    if (write_mask && tid < KK) {
        unsigned int fu = (unsigned int)(keys[tid] >> 32);
        unsigned int bits = (fu & 0x80000000u) ? (fu ^ 0x80000000u) : ~fu;
        float s = __uint_as_float(bits);
        out_mask[(size_t)b * KK + tid] = (s > -1e8f) ? 1.0f : 0.0f;
    }
}

// ---------------------------------------------------------------------------
// Launch. Input order: target_emb, target_category, seq_emb, seq_category,
// seq_mask, [top_k], W. W is located as the LAST input (size D*D) so both
// layouts (with/without a materialized scalar top_k) work.
// ---------------------------------------------------------------------------
extern "C" void kernel_launch(void* const* d_in, const int* in_sizes, int n_in,
                              void* d_out, int out_size)
{
    const float* tgt  = (const float*)d_in[0];
    const float* seq  = (const float*)d_in[2];
    const void*  mask = d_in[4];

    // W: last input of size D*D (search defensively)
    int w_idx = n_in - 1;
    for (int i = n_in - 1; i >= 0; i--) {
        if (in_sizes[i] == DD * DD) { w_idx = i; break; }
    }
    const float* W = (const float*)d_in[w_idx];

    float* out      = (float*)d_out;
    int write_mask  = (out_size >= BB * KK * DD + BB * KK) ? 1 : 0;
    float* out_mask = out + (size_t)BB * KK * DD;

    detect_mask_kernel<<<1, 32>>>((const unsigned int*)mask);
    normalize_mask_kernel<<<(BB * LL + 255) / 256, 256>>>(mask);
    gsu_main_kernel<<<BB, NTHREADS>>>(tgt, seq, W, out, out_mask, write_mask);
}

// round 2
// speedup vs baseline: 2.0464x; 2.0464x over previous
#include <cuda_runtime.h>

#define BB 1024
#define LL 4096
#define DD 64
#define KK 64
#define NTHREADS 256

typedef unsigned long long u64;

__device__ int g_mask_mode; // 0 = int32 {0,1}, 1 = byte bool, 2 = float32 {0,1}

// ---------------------------------------------------------------------------
// Parallel mask dtype detection: 1024 threads each inspect one 32-bit word.
//  int32 bool: every word 0/1.  byte bool: words >1 appear (not 0x3F800000).
//  float bool: 0x3F800000 appears.
// Benign races: threads store the constant 1 -> deterministic.
// ---------------------------------------------------------------------------
__global__ void detect_mask_kernel(const unsigned int* __restrict__ m) {
    __shared__ int f_byte, f_float;
    int tid = threadIdx.x;
    if (tid == 0) { f_byte = 0; f_float = 0; }
    __syncthreads();
    unsigned int w = m[tid];
    if (w == 0x3F800000u) f_float = 1;
    else if (w > 1u)      f_byte = 1;
    __syncthreads();
    if (tid == 0) g_mask_mode = f_float ? 2 : (f_byte ? 1 : 0);
}

// ---------------------------------------------------------------------------
// Main kernel: one CTA per batch row, 8 warps.
//  1) q = (target_emb[b] @ W^T) * 0.125            (exact 1/sqrt(64))
//  2) warp-per-row scoring, coalesced float2 loads + butterfly reduce,
//     mask fused (raw mask read per detected mode), composite-key encode
//  3) partial bitonic top-64 (exact lax.top_k semantics incl. tie-break)
//  4) gather top-64 rows (bit-exact copy) + mask output
// ---------------------------------------------------------------------------
__global__ __launch_bounds__(NTHREADS) void gsu_main_kernel(
    const float* __restrict__ tgt,    // [B, D]
    const float* __restrict__ seq,    // [B, L, D]
    const void*  __restrict__ mraw,   // [B, L] raw mask
    const float* __restrict__ W,      // [D, D]
    float* __restrict__ out_emb,      // [B, K, D]
    float* __restrict__ out_mask,     // [B, K]
    int write_mask)
{
    __shared__ float ts[DD];
    __shared__ float qs[DD];
    __shared__ u64   keys[LL];

    const int b    = blockIdx.x;
    const int tid  = threadIdx.x;
    const int lane = tid & 31;
    const int warp = tid >> 5;

    // --- Step 1: q projection (W stays hot in L2 across all CTAs) ---
    if (tid < DD) ts[tid] = tgt[b * DD + tid];
    __syncthreads();
    if (tid < DD) {
        const float* wr = W + tid * DD;
        float acc = 0.0f;
#pragma unroll
        for (int j = 0; j < DD; j++) acc = fmaf(wr[j], ts[j], acc);
        qs[tid] = acc * 0.125f;
    }
    __syncthreads();

    // --- Step 2: warp-cooperative scoring, coalesced loads ---
    const float qx = qs[2 * lane];
    const float qy = qs[2 * lane + 1];
    const float2* seqb2 = (const float2*)(seq + (size_t)b * LL * DD);
    const int mode = g_mask_mode;

#pragma unroll 1
    for (int g = 0; g < 16; g++) {            // 16 groups of 32 rows per warp
        const int row0 = warp * 512 + g * 32;
        float kept = 0.0f;
#pragma unroll 4
        for (int it = 0; it < 32; it++) {
            float2 v = seqb2[(size_t)(row0 + it) * 32 + lane]; // 256B contiguous/warp
            float s = fmaf(v.y, qy, v.x * qx);
            s += __shfl_xor_sync(0xFFFFFFFFu, s, 16);
            s += __shfl_xor_sync(0xFFFFFFFFu, s, 8);
            s += __shfl_xor_sync(0xFFFFFFFFu, s, 4);
            s += __shfl_xor_sync(0xFFFFFFFFu, s, 2);
            s += __shfl_xor_sync(0xFFFFFFFFu, s, 1);
            if (it == lane) kept = s;          // lane keeps row row0+lane
        }
        const int r = row0 + lane;
        bool valid;
        if (mode == 1)      valid = ((const unsigned char*)mraw)[(size_t)b * LL + r] != 0;
        else if (mode == 2) valid = ((const float*)mraw)[(size_t)b * LL + r] != 0.0f;
        else                valid = ((const int*)mraw)[(size_t)b * LL + r] != 0;
        float s = valid ? kept : -1e9f;
        // order-preserving float->uint; low word encodes lower-index-wins tie-break
        unsigned int fu = __float_as_uint(s);
        fu = (fu & 0x80000000u) ? ~fu : (fu | 0x80000000u);
        keys[r] = ((u64)fu << 32) | (u64)(0xFFFFFFFFu ^ (unsigned)r);
    }
    __syncthreads();

    // --- Step 3a: bitonic stages k=2..64 of the overall-DESC network ---
    // Produces sorted 64-runs alternating desc (even chunks) / asc (odd).
    for (int k = 2; k <= 64; k <<= 1) {
        for (int j = k >> 1; j > 0; j >>= 1) {
#pragma unroll
            for (int u = 0; u < LL / 2 / NTHREADS; u++) {
                const int t   = tid + u * NTHREADS;
                const int i   = ((t & ~(j - 1)) << 1) | (t & (j - 1));
                const int ixj = i | j;
                u64 a = keys[i], c = keys[ixj];
                bool desc = ((i & k) == 0);
                if (desc ? (a < c) : (a > c)) { keys[i] = c; keys[ixj] = a; }
            }
            __syncthreads();
        }
    }

    // --- Step 3b: halving rounds. Pair (desc, asc) chunks form a bitonic
    // 128-block; elementwise max of halves = exact top-64 of the union
    // (bitonic separation lemma), itself bitonic -> 6-phase merge, with
    // direction by new chunk parity so the next round can pair again. ---
    for (int m = 64; m > 1; m >>= 1) {
        const int live = m * 32;              // surviving elements this round
        u64 keep[8];
#pragma unroll
        for (int u = 0; u < 8; u++) {
            const int t = tid + u * NTHREADS;
            if (t < live) {
                const int p = t >> 6, i = t & 63;
                u64 a = keys[p * 128 + i];
                u64 c = keys[p * 128 + 64 + i];
                keep[u] = (a > c) ? a : c;
            }
        }
        __syncthreads();
#pragma unroll
        for (int u = 0; u < 8; u++) {
            const int t = tid + u * NTHREADS;
            if (t < live) keys[t] = keep[u];
        }
        __syncthreads();
        const int half = live >> 1;
        for (int j = 32; j > 0; j >>= 1) {
#pragma unroll
            for (int u = 0; u < 8; u++) {
                const int t = tid + u * NTHREADS;
                if (t < half) {
                    const int i   = ((t & ~(j - 1)) << 1) | (t & (j - 1));
                    const int ixj = i | j;
                    u64 a = keys[i], c = keys[ixj];
                    bool cdesc = (((i >> 6) & 1) == 0);
                    if ((a < c) == cdesc) { keys[i] = c; keys[ixj] = a; }
                }
            }
            __syncthreads();
        }
    }
    // keys[0..63] = exact top-64, descending, jax tie-break.

    // --- Step 4: gather top-K rows (bit-exact copy) ---
    const float4* seqb4 = (const float4*)(seq + (size_t)b * LL * DD);
    float4* out4 = (float4*)(out_emb + (size_t)b * KK * DD);
#pragma unroll
    for (int u = 0; u < KK * DD / 4 / NTHREADS; u++) {
        const int i  = tid + u * NTHREADS;
        const int kk = i >> 4;                 // 16 float4 per row
        const int off = i & 15;
        unsigned int lowk = (unsigned int)keys[kk];
        int idx = (int)(0xFFFFFFFFu ^ lowk);
        out4[i] = seqb4[(size_t)idx * (DD / 4) + off];
    }

    if (write_mask && tid < KK) {
        unsigned int fu = (unsigned int)(keys[tid] >> 32);
        unsigned int bits = (fu & 0x80000000u) ? (fu ^ 0x80000000u) : ~fu;
        float s = __uint_as_float(bits);
        out_mask[(size_t)b * KK + tid] = (s > -1e8f) ? 1.0f : 0.0f;
    }
}

// ---------------------------------------------------------------------------
extern "C" void kernel_launch(void* const* d_in, const int* in_sizes, int n_in,
                              void* d_out, int out_size)
{
    const float* tgt  = (const float*)d_in[0];
    const float* seq  = (const float*)d_in[2];
    const void*  mask = d_in[4];

    int w_idx = n_in - 1;
    for (int i = n_in - 1; i >= 0; i--) {
        if (in_sizes[i] == DD * DD) { w_idx = i; break; }
    }
    const float* W = (const float*)d_in[w_idx];

    float* out      = (float*)d_out;
    int write_mask  = (out_size >= BB * KK * DD + BB * KK) ? 1 : 0;
    float* out_mask = out + (size_t)BB * KK * DD;

    detect_mask_kernel<<<1, 1024>>>((const unsigned int*)mask);
    gsu_main_kernel<<<BB, NTHREADS>>>(tgt, seq, mask, W, out, out_mask, write_mask);
}

// round 3
// speedup vs baseline: 2.1299x; 1.0408x over previous
#include <cuda_runtime.h>

#define BB 1024
#define LL 4096
#define DD 64
#define KK 64
#define NTHREADS 256
#define NWARPS 8
#define ROWS_PER_WARP (LL / NWARPS)      // 512
#define TROWS 8                          // rows per tile
#define NTILES (ROWS_PER_WARP / TROWS)   // 64
#define SMEM_TOTAL (32768 + 32768 + 2 * DD * 4)

typedef unsigned long long u64;

__device__ int g_mask_mode; // 0 = int32 {0,1}, 1 = byte bool, 2 = float32 {0,1}

// ---------------------------------------------------------------------------
__global__ void detect_mask_kernel(const unsigned int* __restrict__ m) {
    __shared__ int f_byte, f_float;
    int tid = threadIdx.x;
    if (tid == 0) { f_byte = 0; f_float = 0; }
    __syncthreads();
    unsigned int w = m[tid];
    if (w == 0x3F800000u) f_float = 1;
    else if (w > 1u)      f_byte = 1;
    __syncthreads();
    if (tid == 0) g_mask_mode = f_float ? 2 : (f_byte ? 1 : 0);
}

__device__ __forceinline__ void cp_async16(unsigned int saddr, const void* g) {
    asm volatile("cp.async.cg.shared.global [%0], [%1], 16;" :: "r"(saddr), "l"(g));
}
__device__ __forceinline__ void cp_commit() {
    asm volatile("cp.async.commit_group;");
}

// ---------------------------------------------------------------------------
// One CTA per batch row, 8 warps, 66KB dynamic smem.
//  1) q = (target_emb[b] @ W^T) * 0.125
//  2) double-buffered cp.async tile staging + smem-transposed scoring
//     (2 shuffles per 8 rows instead of 5 per row)
//  3) partial bitonic top-64 (exact lax.top_k semantics incl. tie-break)
//  4) gather top-64 rows (bit-exact) + mask output
// ---------------------------------------------------------------------------
__global__ __launch_bounds__(NTHREADS) void gsu_main_kernel(
    const float* __restrict__ tgt,
    const float* __restrict__ seq,
    const void*  __restrict__ mraw,
    const float* __restrict__ W,
    float* __restrict__ out_emb,
    float* __restrict__ out_mask,
    int write_mask)
{
    extern __shared__ char sraw[];
    u64*    keys  = (u64*)sraw;                         // 32768 B
    float4* tiles = (float4*)(sraw + 32768);            // 32768 B: [warp][buf][row8][16]
    float*  ts    = (float*)(sraw + 65536);
    float*  qs    = ts + DD;

    const int b    = blockIdx.x;
    const int tid  = threadIdx.x;
    const int lane = tid & 31;
    const int warp = tid >> 5;

    // --- Step 1: q projection ---
    if (tid < DD) ts[tid] = tgt[b * DD + tid];
    __syncthreads();
    if (tid < DD) {
        const float* wr = W + tid * DD;
        float acc = 0.0f;
#pragma unroll
        for (int j = 0; j < DD; j++) acc = fmaf(wr[j], ts[j], acc);
        qs[tid] = acc * 0.125f; // exact 1/sqrt(64)
    }
    __syncthreads();

    // --- Step 2: staged scoring ---
    const int r     = lane & 7;        // row within tile
    const int piece = lane >> 3;       // 16-dim slice
    const float4* q4s = (const float4*)qs;
    float4 qr[4];
#pragma unroll
    for (int j = 0; j < 4; j++) qr[j] = q4s[piece * 4 + j];

    const float4* seq4 = (const float4*)(seq + (size_t)b * LL * DD);
    const int wrow0 = warp * ROWS_PER_WARP;
    float4* twarp = tiles + warp * 256;                 // 2 bufs * 128 float4
    unsigned int tbase = (unsigned int)__cvta_generic_to_shared(twarp);
    const int mode = g_mask_mode;

    // issue tile t into buffer buf
    auto issue = [&](int t, int buf) {
#pragma unroll
        for (int it = 0; it < 4; it++) {
            const int idx  = it * 32 + lane;            // 0..127 float4 in tile
            const int trow = idx >> 4, tcol = idx & 15;
            unsigned int dst = tbase + (unsigned)((buf * 128 + trow * 16 + (tcol ^ trow)) << 4);
            cp_async16(dst, seq4 + (size_t)(wrow0 + t * TROWS) * 16 + idx);
        }
        cp_commit();
    };

    issue(0, 0);
#pragma unroll 1
    for (int t = 0; t < NTILES; t++) {
        const int buf = t & 1;
        if (t + 1 < NTILES) {
            issue(t + 1, (t + 1) & 1);
            asm volatile("cp.async.wait_group 1;");
        } else {
            asm volatile("cp.async.wait_group 0;");
        }
        __syncwarp();

        const float4* tb = twarp + buf * 128 + r * 16;
        float4 v0 = tb[(piece * 4 + 0) ^ r];
        float4 v1 = tb[(piece * 4 + 1) ^ r];
        float4 v2 = tb[(piece * 4 + 2) ^ r];
        float4 v3 = tb[(piece * 4 + 3) ^ r];
        float s = v0.x * qr[0].x;
        s = fmaf(v0.y, qr[0].y, s); s = fmaf(v0.z, qr[0].z, s); s = fmaf(v0.w, qr[0].w, s);
        s = fmaf(v1.x, qr[1].x, s); s = fmaf(v1.y, qr[1].y, s);
        s = fmaf(v1.z, qr[1].z, s); s = fmaf(v1.w, qr[1].w, s);
        s = fmaf(v2.x, qr[2].x, s); s = fmaf(v2.y, qr[2].y, s);
        s = fmaf(v2.z, qr[2].z, s); s = fmaf(v2.w, qr[2].w, s);
        s = fmaf(v3.x, qr[3].x, s); s = fmaf(v3.y, qr[3].y, s);
        s = fmaf(v3.z, qr[3].z, s); s = fmaf(v3.w, qr[3].w, s);
        s += __shfl_xor_sync(0xFFFFFFFFu, s, 8);
        s += __shfl_xor_sync(0xFFFFFFFFu, s, 16);
        __syncwarp();

        if (lane < TROWS) {
            const int row = wrow0 + t * TROWS + r;
            bool valid;
            if (mode == 1)      valid = ((const unsigned char*)mraw)[(size_t)b * LL + row] != 0;
            else if (mode == 2) valid = ((const float*)mraw)[(size_t)b * LL + row] != 0.0f;
            else                valid = ((const int*)mraw)[(size_t)b * LL + row] != 0;
            float sv = valid ? s : -1e9f;
            unsigned int fu = __float_as_uint(sv);
            fu = (fu & 0x80000000u) ? ~fu : (fu | 0x80000000u);
            keys[row] = ((u64)fu << 32) | (u64)(0xFFFFFFFFu ^ (unsigned)row);
        }
    }
    __syncthreads();

    // --- Step 3a: bitonic stages k=2..64 (alternating desc/asc 64-runs) ---
    for (int k = 2; k <= 64; k <<= 1) {
        for (int j = k >> 1; j > 0; j >>= 1) {
#pragma unroll
            for (int u = 0; u < LL / 2 / NTHREADS; u++) {
                const int t   = tid + u * NTHREADS;
                const int i   = ((t & ~(j - 1)) << 1) | (t & (j - 1));
                const int ixj = i | j;
                u64 a = keys[i], c = keys[ixj];
                bool desc = ((i & k) == 0);
                if (desc ? (a < c) : (a > c)) { keys[i] = c; keys[ixj] = a; }
            }
            __syncthreads();
        }
    }

    // --- Step 3b: halving rounds (bitonic separation + 6-phase merge) ---
    for (int m = 64; m > 1; m >>= 1) {
        const int live = m * 32;
        u64 keep[8];
#pragma unroll
        for (int u = 0; u < 8; u++) {
            const int t = tid + u * NTHREADS;
            if (t < live) {
                const int p = t >> 6, i = t & 63;
                u64 a = keys[p * 128 + i];
                u64 c = keys[p * 128 + 64 + i];
                keep[u] = (a > c) ? a : c;
            }
        }
        __syncthreads();
#pragma unroll
        for (int u = 0; u < 8; u++) {
            const int t = tid + u * NTHREADS;
            if (t < live) keys[t] = keep[u];
        }
        __syncthreads();
        const int half = live >> 1;
        for (int j = 32; j > 0; j >>= 1) {
#pragma unroll
            for (int u = 0; u < 8; u++) {
                const int t = tid + u * NTHREADS;
                if (t < half) {
                    const int i   = ((t & ~(j - 1)) << 1) | (t & (j - 1));
                    const int ixj = i | j;
                    u64 a = keys[i], c = keys[ixj];
                    bool cdesc = (((i >> 6) & 1) == 0);
                    if ((a < c) == cdesc) { keys[i] = c; keys[ixj] = a; }
                }
            }
            __syncthreads();
        }
    }
    // keys[0..63] = exact top-64, descending, jax tie-break.

    // --- Step 4: gather top-K rows (bit-exact copy) ---
    float4* out4 = (float4*)(out_emb + (size_t)b * KK * DD);
#pragma unroll
    for (int u = 0; u < KK * DD / 4 / NTHREADS; u++) {
        const int i   = tid + u * NTHREADS;
        const int kk  = i >> 4;
        const int off = i & 15;
        unsigned int lowk = (unsigned int)keys[kk];
        int idx = (int)(0xFFFFFFFFu ^ lowk);
        out4[i] = seq4[(size_t)idx * (DD / 4) + off];
    }

    if (write_mask && tid < KK) {
        unsigned int fu = (unsigned int)(keys[tid] >> 32);
        unsigned int bits = (fu & 0x80000000u) ? (fu ^ 0x80000000u) : ~fu;
        float s = __uint_as_float(bits);
        out_mask[(size_t)b * KK + tid] = (s > -1e8f) ? 1.0f : 0.0f;
    }
}

// ---------------------------------------------------------------------------
extern "C" void kernel_launch(void* const* d_in, const int* in_sizes, int n_in,
                              void* d_out, int out_size)
{
    const float* tgt  = (const float*)d_in[0];
    const float* seq  = (const float*)d_in[2];
    const void*  mask = d_in[4];

    int w_idx = n_in - 1;
    for (int i = n_in - 1; i >= 0; i--) {
        if (in_sizes[i] == DD * DD) { w_idx = i; break; }
    }
    const float* W = (const float*)d_in[w_idx];

    float* out      = (float*)d_out;
    int write_mask  = (out_size >= BB * KK * DD + BB * KK) ? 1 : 0;
    float* out_mask = out + (size_t)BB * KK * DD;

    cudaFuncSetAttribute(gsu_main_kernel,
                         cudaFuncAttributeMaxDynamicSharedMemorySize, SMEM_TOTAL);

    detect_mask_kernel<<<1, 1024>>>((const unsigned int*)mask);
    gsu_main_kernel<<<BB, NTHREADS, SMEM_TOTAL>>>(tgt, seq, mask, W, out, out_mask, write_mask);
}

// round 4
// speedup vs baseline: 2.7051x; 1.2701x over previous
#include <cuda_runtime.h>

#define BB 1024
#define LL 4096
#define DD 64
#define KK 64
#define NCHUNK 4
#define CROWS (LL / NCHUNK)       // 1024 rows per chunk
#define NTHREADS 256
#define NWARPS 8
#define WR (CROWS / NWARPS)       // 128 rows per warp
#define NTILES (WR / 8)           // 16 tiles of 8 rows

typedef unsigned long long u64;

__device__ int g_mask_mode;                 // 0=int32, 1=byte, 2=float32
__device__ u64 g_part[BB * NCHUNK * KK];    // 2 MB chunk-top64 scratch

// ---------------------------------------------------------------------------
__global__ void detect_mask_kernel(const unsigned int* __restrict__ m) {
    __shared__ int f_byte, f_float;
    int tid = threadIdx.x;
    if (tid == 0) { f_byte = 0; f_float = 0; }
    __syncthreads();
    unsigned int w = m[tid];
    if (w == 0x3F800000u) f_float = 1;
    else if (w > 1u)      f_byte = 1;
    __syncthreads();
    if (tid == 0) g_mask_mode = f_float ? 2 : (f_byte ? 1 : 0);
}

__device__ __forceinline__ void cp_async16(unsigned int saddr, const void* g) {
    asm volatile("cp.async.cg.shared.global [%0], [%1], 16;" :: "r"(saddr), "l"(g));
}

// ---------------------------------------------------------------------------
// Kernel A: one CTA per (batch, chunk). Scores 1024 rows, selects exact
// chunk top-64 (composite keys: score-ordered uint + lower-index tie-break),
// writes 64 keys to g_part.
// ---------------------------------------------------------------------------
__global__ __launch_bounds__(NTHREADS) void gsu_score_kernel(
    const float* __restrict__ tgt,
    const float* __restrict__ seq,
    const void*  __restrict__ mraw,
    const float* __restrict__ W)
{
    __shared__ u64 keys[CROWS];                         // 8 KB
    __shared__ float4 tiles[NWARPS * 2 * 128];          // 32 KB
    __shared__ float ts[DD];
    __shared__ float qs[DD];
    __shared__ unsigned char smask[CROWS];              // 1 KB

    const int b   = blockIdx.x >> 2;
    const int c   = blockIdx.x & 3;
    const int tid = threadIdx.x;
    const int lane = tid & 31;
    const int warp = tid >> 5;

    // --- target vector + normalized mask chunk ---
    if (tid < DD) ts[tid] = tgt[b * DD + tid];
    {
        const int mode = g_mask_mode;
        const size_t mbase = (size_t)b * LL + (size_t)c * CROWS;
        for (int i = tid; i < CROWS; i += NTHREADS) {
            bool v;
            if (mode == 1)      v = ((const unsigned char*)mraw)[mbase + i] != 0;
            else if (mode == 2) v = ((const float*)mraw)[mbase + i] != 0.0f;
            else                v = ((const int*)mraw)[mbase + i] != 0;
            smask[i] = (unsigned char)v;
        }
    }
    __syncthreads();

    // --- q = (tgt @ W^T) * 1/8 ---
    if (tid < DD) {
        const float* wr = W + tid * DD;
        float acc = 0.0f;
#pragma unroll
        for (int j = 0; j < DD; j++) acc = fmaf(wr[j], ts[j], acc);
        qs[tid] = acc * 0.125f;
    }
    __syncthreads();

    // --- scoring: per-warp double-buffered cp.async pipeline ---
    const int r     = lane & 7;
    const int piece = lane >> 3;
    float4 qr[4];
#pragma unroll
    for (int j = 0; j < 4; j++) qr[j] = ((const float4*)qs)[piece * 4 + j];

    const float4* seq4 = (const float4*)(seq + ((size_t)b * LL + (size_t)c * CROWS) * DD);
    float4* twarp = tiles + warp * 256;
    const unsigned int tbase = (unsigned int)__cvta_generic_to_shared(twarp);

    // hoisted per-thread constants
    unsigned int dstoff[4];
#pragma unroll
    for (int it = 0; it < 4; it++) {
        const int idx  = it * 32 + lane;
        const int trow = idx >> 4, tcol = idx & 15;
        dstoff[it] = tbase + (unsigned)((trow * 16 + (tcol ^ trow)) << 4);
    }
    const int i0 = (piece * 4 + 0) ^ r;
    const int i1 = (piece * 4 + 1) ^ r;
    const int i2 = (piece * 4 + 2) ^ r;
    const int i3 = (piece * 4 + 3) ^ r;
    const float4* tb0 = twarp + r * 16;
    const float4* tb1 = twarp + 128 + r * 16;
    const float4* src = seq4 + (size_t)(warp * WR) * 16 + lane;   // +128/tile

    // issue tile t into buffer (t&1)
    {
#pragma unroll
        for (int it = 0; it < 4; it++)
            cp_async16(dstoff[it], src + it * 32);
        asm volatile("cp.async.commit_group;");
    }
#pragma unroll 1
    for (int t = 0; t < NTILES; t++) {
        if (t + 1 < NTILES) {
            const unsigned int bufo = ((t + 1) & 1) ? 2048u : 0u;
            const float4* s2 = src + (t + 1) * 128;
#pragma unroll
            for (int it = 0; it < 4; it++)
                cp_async16(dstoff[it] + bufo, s2 + it * 32);
            asm volatile("cp.async.commit_group;");
            asm volatile("cp.async.wait_group 1;");
        } else {
            asm volatile("cp.async.wait_group 0;");
        }
        __syncwarp();

        const float4* tb = (t & 1) ? tb1 : tb0;
        float4 v0 = tb[i0], v1 = tb[i1], v2 = tb[i2], v3 = tb[i3];
        float s = v0.x * qr[0].x;
        s = fmaf(v0.y, qr[0].y, s); s = fmaf(v0.z, qr[0].z, s); s = fmaf(v0.w, qr[0].w, s);
        s = fmaf(v1.x, qr[1].x, s); s = fmaf(v1.y, qr[1].y, s);
        s = fmaf(v1.z, qr[1].z, s); s = fmaf(v1.w, qr[1].w, s);
        s = fmaf(v2.x, qr[2].x, s); s = fmaf(v2.y, qr[2].y, s);
        s = fmaf(v2.z, qr[2].z, s); s = fmaf(v2.w, qr[2].w, s);
        s = fmaf(v3.x, qr[3].x, s); s = fmaf(v3.y, qr[3].y, s);
        s = fmaf(v3.z, qr[3].z, s); s = fmaf(v3.w, qr[3].w, s);
        s += __shfl_xor_sync(0xFFFFFFFFu, s, 8);
        s += __shfl_xor_sync(0xFFFFFFFFu, s, 16);
        __syncwarp();

        if (lane < 8) {
            const int lrow = warp * WR + t * 8 + r;       // row within chunk
            const int grow = c * CROWS + lrow;            // row within batch
            float sv = smask[lrow] ? s : -1e9f;
            unsigned int fu = __float_as_uint(sv);
            fu = (fu & 0x80000000u) ? ~fu : (fu | 0x80000000u);
            keys[lrow] = ((u64)fu << 32) | (u64)(0xFFFFFFFFu ^ (unsigned)grow);
        }
    }
    __syncthreads();

    // --- partial bitonic top-64 on 1024 keys ---
    for (int k = 2; k <= 64; k <<= 1) {
        for (int j = k >> 1; j > 0; j >>= 1) {
#pragma unroll
            for (int u = 0; u < CROWS / 2 / NTHREADS; u++) {
                const int t   = tid + u * NTHREADS;
                const int i   = ((t & ~(j - 1)) << 1) | (t & (j - 1));
                const int ixj = i | j;
                u64 a = keys[i], cc = keys[ixj];
                bool desc = ((i & k) == 0);
                if (desc ? (a < cc) : (a > cc)) { keys[i] = cc; keys[ixj] = a; }
            }
            __syncthreads();
        }
    }
    // halving rounds: live = post-compaction count
    for (int live = CROWS / 2; live >= 64; live >>= 1) {
        u64 keep[2];
#pragma unroll
        for (int u = 0; u < 2; u++) {
            const int t = tid + u * NTHREADS;
            if (t < live) {
                const int p = t >> 6, i = t & 63;
                u64 a = keys[p * 128 + i];
                u64 cc = keys[p * 128 + 64 + i];
                keep[u] = (a > cc) ? a : cc;
            }
        }
        __syncthreads();
#pragma unroll
        for (int u = 0; u < 2; u++) {
            const int t = tid + u * NTHREADS;
            if (t < live) keys[t] = keep[u];
        }
        __syncthreads();
        for (int j = 32; j > 0; j >>= 1) {
#pragma unroll
            for (int u = 0; u < 2; u++) {
                const int t = tid + u * NTHREADS;
                if (t < live / 2) {
                    const int i   = ((t & ~(j - 1)) << 1) | (t & (j - 1));
                    const int ixj = i | j;
                    u64 a = keys[i], cc = keys[ixj];
                    bool cdesc = (((i >> 6) & 1) == 0);
                    if ((a < cc) == cdesc) { keys[i] = cc; keys[ixj] = a; }
                }
            }
            __syncthreads();
        }
    }

    if (tid < KK) g_part[(size_t)blockIdx.x * KK + tid] = keys[tid];
}

// ---------------------------------------------------------------------------
// Kernel B: merge 4 chunk-top64 lists (exact), gather rows, write mask.
// ---------------------------------------------------------------------------
__global__ __launch_bounds__(NTHREADS) void gsu_merge_kernel(
    const float* __restrict__ seq,
    float* __restrict__ out_emb,
    float* __restrict__ out_mask,
    int write_mask)
{
    __shared__ u64 skeys[NCHUNK * KK];   // 256 keys
    const int b   = blockIdx.x;
    const int tid = threadIdx.x;

    if (tid < NCHUNK * KK) {
        const int cidx = tid >> 6, i = tid & 63;
        const int srci = (cidx & 1) ? (63 - i) : i;   // odd chunks reversed -> asc
        skeys[tid] = g_part[((size_t)b * NCHUNK + cidx) * KK + srci];
    }
    __syncthreads();

    for (int live = 128; live >= 64; live >>= 1) {
        u64 kp = 0;
        const bool act = tid < live;
        if (act) {
            const int p = tid >> 6, i = tid & 63;
            u64 a = skeys[p * 128 + i];
            u64 cc = skeys[p * 128 + 64 + i];
            kp = (a > cc) ? a : cc;
        }
        __syncthreads();
        if (act) skeys[tid] = kp;
        __syncthreads();
        for (int j = 32; j > 0; j >>= 1) {
            if (tid < live / 2) {
                const int i   = ((tid & ~(j - 1)) << 1) | (tid & (j - 1));
                const int ixj = i | j;
                u64 a = skeys[i], cc = skeys[ixj];
                bool cdesc = (((i >> 6) & 1) == 0);
                if ((a < cc) == cdesc) { skeys[i] = cc; skeys[ixj] = a; }
            }
            __syncthreads();
        }
    }
    // skeys[0..63] = exact global top-64, descending, jax tie-break.

    const float4* seq4 = (const float4*)(seq + (size_t)b * LL * DD);
    float4* out4 = (float4*)(out_emb + (size_t)b * KK * DD);
#pragma unroll
    for (int u = 0; u < KK * DD / 4 / NTHREADS; u++) {
        const int i   = tid + u * NTHREADS;
        const int kk  = i >> 4;
        const int off = i & 15;
        const int idx = (int)(0xFFFFFFFFu ^ (unsigned int)skeys[kk]);
        out4[i] = seq4[(size_t)idx * (DD / 4) + off];
    }

    if (write_mask && tid < KK) {
        unsigned int fu = (unsigned int)(skeys[tid] >> 32);
        unsigned int bits = (fu & 0x80000000u) ? (fu ^ 0x80000000u) : ~fu;
        float s = __uint_as_float(bits);
        out_mask[(size_t)b * KK + tid] = (s > -1e8f) ? 1.0f : 0.0f;
    }
}

// ---------------------------------------------------------------------------
extern "C" void kernel_launch(void* const* d_in, const int* in_sizes, int n_in,
                              void* d_out, int out_size)
{
    const float* tgt  = (const float*)d_in[0];
    const float* seq  = (const float*)d_in[2];
    const void*  mask = d_in[4];

    int w_idx = n_in - 1;
    for (int i = n_in - 1; i >= 0; i--) {
        if (in_sizes[i] == DD * DD) { w_idx = i; break; }
    }
    const float* W = (const float*)d_in[w_idx];

    float* out      = (float*)d_out;
    int write_mask  = (out_size >= BB * KK * DD + BB * KK) ? 1 : 0;
    float* out_mask = out + (size_t)BB * KK * DD;

    detect_mask_kernel<<<1, 1024>>>((const unsigned int*)mask);
    gsu_score_kernel<<<BB * NCHUNK, NTHREADS>>>(tgt, seq, mask, W);
    gsu_merge_kernel<<<BB, NTHREADS>>>(seq, out, out_mask, write_mask);
}